// round 16
// baseline (speedup 1.0000x reference)
#include <cuda_runtime.h>
#include <cuda_bf16.h>
#include <cstdint>

// Problem constants
#define BB 16
#define CC 16
#define PP 256          // patches per image (16x16)
#define DD 4096         // flattened patch dim
#define EE 512          // embedding dim
#define MROWS 4096      // B*P
#define N1 1024         // theta|f concat
#define KSTACK 12288    // 3*DD (hi/lo stacked K)
#define KLOG 1536       // 3*EE (hi/lo stacked logits K)
#define NTILES 1472     // 256 mode0 + 192 mode1 + 64 logits + 832 mode1 + 128 epilogue

// ---------------- scratch (device globals; no allocation allowed) ----------------
__device__ __nv_bfloat16 g_p_hi[(size_t)MROWS * DD];
__device__ __nv_bfloat16 g_p_lo[(size_t)MROWS * DD];
__device__ __nv_bfloat16 g_w1t[(size_t)N1 * KSTACK];      // [n, kstack]: Whi | Whi | Wlo
__device__ __nv_bfloat16 g_gwt[(size_t)DD * DD];          // g_w transposed [n, k]
__device__ __nv_bfloat16 g_lA[(size_t)MROWS * KLOG];      // [thetahi | thetalo | thetahi] (+bias)
__device__ __nv_bfloat16 g_lB[(size_t)MROWS * KLOG];      // [fhi | fhi | flo] (+bias)
__device__ __nv_bfloat16 g_gm_bf[(size_t)MROWS * DD];     // g = p @ g_w (bf16)
__device__ float g_att[(size_t)BB * PP * PP];             // raw logits
__device__ unsigned int g_tile_ctr;                       // persistent-GEMM work counter
__device__ unsigned int g_done_ctr;                       // mode-0 tile completions
__device__ unsigned int g_g_done[32];                     // mode-1 completions per M-band (target 32)
__device__ unsigned int g_l_done[32];                     // logits completions per 128-row band (target 2)

__device__ __forceinline__ uint32_t smem_u32(const void* p) {
    uint32_t a;
    asm("{ .reg .u64 t; cvta.to.shared.u64 t, %1; cvt.u32.u64 %0, t; }" : "=r"(a) : "l"(p));
    return a;
}
__device__ __forceinline__ void cp_async16(uint32_t saddr, const void* gptr) {
    asm volatile("cp.async.cg.shared.global [%0], [%1], 16;" :: "r"(saddr), "l"(gptr));
}
__device__ __forceinline__ void cp_commit() {
    asm volatile("cp.async.commit_group;");
}
template <int N>
__device__ __forceinline__ void cp_wait() {
    asm volatile("cp.async.wait_group %0;" :: "n"(N));
}
__device__ __forceinline__ void ldsm_x4(uint32_t* r, uint32_t addr) {
    asm volatile("ldmatrix.sync.aligned.m8n8.x4.shared.b16 {%0,%1,%2,%3}, [%4];"
                 : "=r"(r[0]), "=r"(r[1]), "=r"(r[2]), "=r"(r[3]) : "r"(addr));
}
__device__ __forceinline__ void mma16816(float* d, const uint32_t* a, const uint32_t* b) {
    asm volatile(
        "mma.sync.aligned.m16n8k16.row.col.f32.bf16.bf16.f32 "
        "{%0,%1,%2,%3}, {%4,%5,%6,%7}, {%8,%9}, {%0,%1,%2,%3};"
        : "+f"(d[0]), "+f"(d[1]), "+f"(d[2]), "+f"(d[3])
        : "r"(a[0]), "r"(a[1]), "r"(a[2]), "r"(a[3]), "r"(b[0]), "r"(b[1]));
}

// ---------------- kernel 1: prep (patch extract + hi/lo) MERGED with weight transforms ----------------
__global__ __launch_bounds__(256) void prep_kernel(const float* __restrict__ x,
                                                   const float* __restrict__ theta_w,
                                                   const float* __restrict__ f_w,
                                                   const float* __restrict__ gw) {
    const int bid = blockIdx.x;
    const int tid = threadIdx.x;
    if (bid == 0) {   // reset all persistent-kernel counters each replay
        if (tid == 0) { g_tile_ctr = 0u; g_done_ctr = 0u; }
        if (tid < 32) { g_g_done[tid] = 0u; g_l_done[tid] = 0u; }
    }
    if (bid < 16384) {
        // patch extract + bf16 hi/lo split
        size_t i4 = (size_t)bid * 256 + tid;
        size_t e0 = i4 << 2;  // element index into p [4096, 4096]
        int d   = (int)(e0 & 4095);
        int row = (int)(e0 >> 12);
        int b = row >> 8, p = row & 255;
        int pi = p >> 4, pj = p & 15;
        int c = d >> 8, rem = d & 255;
        int ih = rem >> 4, iw = rem & 15;
        size_t xi = (((((size_t)b * CC + c) << 8) + (pi << 4) + ih) << 8) + (pj << 4) + iw;
        float4 v = *(const float4*)(x + xi);
        float vv[4] = {v.x, v.y, v.z, v.w};
        __nv_bfloat16 h[4], l[4];
#pragma unroll
        for (int j = 0; j < 4; ++j) {
            h[j] = __float2bfloat16(vv[j]);
            l[j] = __float2bfloat16(vv[j] - __bfloat162float(h[j]));
        }
        ((__nv_bfloat162*)(g_p_hi + e0))[0] = __nv_bfloat162(h[0], h[1]);
        ((__nv_bfloat162*)(g_p_hi + e0))[1] = __nv_bfloat162(h[2], h[3]);
        ((__nv_bfloat162*)(g_p_lo + e0))[0] = __nv_bfloat162(l[0], l[1]);
        ((__nv_bfloat162*)(g_p_lo + e0))[1] = __nv_bfloat162(l[2], l[3]);
    } else {
        // weight transforms (32x32 transpose tiles, 256 threads do 8 rows/pass)
        __shared__ float s[32][33];
        int wb = bid - 16384;            // 0..20479
        int k0 = (wb & 127) << 5;
        int wy = wb >> 7;                // 0..159
        int tx = tid & 31, tg = tid >> 5;
        if (wy < 32) {
            int n0 = wy << 5;
            int n = n0 + tx;
#pragma unroll
            for (int rr = tg; rr < 32; rr += 8)
                s[rr][tx] = (n < EE) ? theta_w[(size_t)(k0 + rr) * EE + n]
                                     : f_w[(size_t)(k0 + rr) * EE + (n - EE)];
            __syncthreads();
#pragma unroll
            for (int rr = tg; rr < 32; rr += 8) {
                int k = k0 + tx, nn = n0 + rr;
                float w = s[tx][rr];
                __nv_bfloat16 hi = __float2bfloat16(w);
                __nv_bfloat16 lo = __float2bfloat16(w - __bfloat162float(hi));
                size_t base = (size_t)nn * KSTACK + k;
                g_w1t[base]        = hi;
                g_w1t[base + 4096] = hi;
                g_w1t[base + 8192] = lo;
            }
        } else {
            int n0 = (wy - 32) << 5;
#pragma unroll
            for (int rr = tg; rr < 32; rr += 8)
                s[rr][tx] = gw[(size_t)(k0 + rr) * DD + (n0 + tx)];
            __syncthreads();
#pragma unroll
            for (int rr = tg; rr < 32; rr += 8)
                g_gwt[(size_t)(n0 + rr) * DD + (k0 + tx)] = __float2bfloat16(s[tx][rr]);
        }
    }
}

// ---------------- kernel 2: persistent merged HMMA GEMM + fused epilogue (4 tile modes) ----------------
// t <  256          : mode0 TF = [p_hi|p_lo|p_hi] @ W1t^T (K=12288) -> bias + hi/lo split into g_lA/g_lB
// 256<=t<448, 512<=t<1344 : mode1 g = p_hi @ gwt^T        (K=4096)  -> bf16 g_gm_bf
// 448<=t<512        : mode2 logits = lA @ lB^T            (K=1536)  -> fp32 g_att (waits for all mode0)
// t >= 1344         : mode3 epilogue: softmax + gate + residual (waits per-band on mode1 + logits)
#define STAGES 3
#define STAGE_BYTES 32768      // A tile 16KB + B tile 16KB
#define GEMM_SMEM (STAGES * STAGE_BYTES + 16)

__global__ __launch_bounds__(128, 2) void gemm_hmma_kernel(const float* __restrict__ theta_b,
                                                           const float* __restrict__ f_b,
                                                           const float* __restrict__ x,
                                                           const float* __restrict__ gb,
                                                           const float* __restrict__ scale,
                                                           float* __restrict__ out) {
    extern __shared__ __align__(1024) char smem[];
    int* s_tile = (int*)(smem + STAGES * STAGE_BYTES);

    const int tid = threadIdx.x;
    const int lane = tid & 31, wid = tid >> 5;
    const uint32_t sbase = smem_u32(smem);

    const int chunk = tid & 7;       // 8 chunks of 16B per 128B row
    const int lrow  = tid >> 3;      // 0..15

    // warp tiling: 2 (M) x 2 (N) warps; warp tile 64x64
    const int m_off = (wid & 1) << 6;
    const int n_off = (wid >> 1) << 6;
    const int arow  = lane & 15;
    const int acolb = (lane >> 4) << 4;
    const int brow  = (lane & 7) + ((lane >> 4) << 3);
    const int bcolb = (lane & 8) << 1;

    while (true) {
        if (tid == 0) *s_tile = (int)atomicAdd(&g_tile_ctr, 1u);
        __syncthreads();          // broadcast tile id; also fences previous tile's smem reads
        const int t = *s_tile;
        if (t >= NTILES) break;

        // ---------------- mode3: fused softmax + gating epilogue tile (32 rows) ----------------
        if (t >= 1344) {
            int r0 = (t - 1344) << 5;
            int band = r0 >> 7;
            if (tid == 0) {
                while (*(volatile unsigned int*)&g_l_done[band] < 2u) __nanosleep(64);
                while (*(volatile unsigned int*)&g_g_done[band] < 32u) __nanosleep(64);
            }
            __syncthreads();
            __threadfence();   // acquire
            float* swv = (float*)smem;   // 4 warps x 256 floats (GEMM smem idle here)
            float sc = scale[0];
            for (int rr = wid; rr < 32; rr += 4) {
                int row = r0 + rr;
                float v[8];
#pragma unroll
                for (int j = 0; j < 8; ++j) v[j] = g_att[(size_t)row * PP + (j << 5) + lane];
                float M = v[0];
#pragma unroll
                for (int j = 1; j < 8; ++j) M = fmaxf(M, v[j]);
#pragma unroll
                for (int o = 16; o; o >>= 1) M = fmaxf(M, __shfl_xor_sync(0xffffffffu, M, o));
                float s = 0.f;
#pragma unroll
                for (int j = 0; j < 8; ++j) { v[j] = __expf(v[j] - M); s += v[j]; }
#pragma unroll
                for (int o = 16; o; o >>= 1) s += __shfl_xor_sync(0xffffffffu, s, o);
                float inv = 1.f / s;
#pragma unroll
                for (int j = 0; j < 8; ++j) swv[(wid << 8) + (j << 5) + lane] = v[j] * inv;
                __syncwarp();
                int b = row >> 8, p = row & 255;
                int pi = p >> 4, pj = p & 15;
#pragma unroll 4
                for (int c = 0; c < 16; ++c) {
#pragma unroll
                    for (int nb = 0; nb < 2; ++nb) {
                        int n0 = ((nb << 5) + lane) << 2;
                        float4 wv = *(float4*)&swv[(wid << 8) + n0];
                        const __nv_bfloat162* gp =
                            (const __nv_bfloat162*)(g_gm_bf + (size_t)row * DD + (c << 8) + n0);
                        __nv_bfloat162 g01 = gp[0], g23 = gp[1];
                        float4 gbv = *(const float4*)(gb + (c << 8) + n0);
                        int ih = n0 >> 4, iw = n0 & 15;
                        size_t xo = ((((size_t)(b * CC + c) << 8) + (pi << 4) + ih) << 8) + (pj << 4) + iw;
                        float4 xv = *(const float4*)(x + xo);
                        float4 o4;
                        o4.x = sc * wv.x * (__bfloat162float(g01.x) + gbv.x) + xv.x;
                        o4.y = sc * wv.y * (__bfloat162float(g01.y) + gbv.y) + xv.y;
                        o4.z = sc * wv.z * (__bfloat162float(g23.x) + gbv.z) + xv.z;
                        o4.w = sc * wv.w * (__bfloat162float(g23.y) + gbv.w) + xv.w;
                        *(float4*)(out + xo) = o4;
                    }
                }
                __syncwarp();   // before next row reuses swv region
            }
            continue;
        }

        int mode, bx = 0, by = 0, q0 = 0, l_band = 0;
        size_t aRow0, bRow0;
        int sAe, sBe, nkb;
        const __nv_bfloat16 *Abase = g_p_hi, *Bbase;

        if (t < 256) {
            mode = 0; bx = t & 7; by = t >> 3;
            aRow0 = (size_t)by << 7; bRow0 = (size_t)bx << 7;
            sAe = DD; sBe = KSTACK; Bbase = g_w1t; nkb = KSTACK >> 6;
        } else if (t >= 448 && t < 512) {
            mode = 2;
            int u = t - 448;
            l_band = u >> 1;
            int b = u >> 2;
            aRow0 = (size_t)b * PP + (size_t)((u >> 1) & 1) * 128;
            q0 = (u & 1) << 7;
            bRow0 = (size_t)b * PP + q0;
            sAe = KLOG; sBe = KLOG; Abase = g_lA; Bbase = g_lB; nkb = KLOG >> 6;
        } else {
            mode = 1;
            int u = (t < 448) ? (t - 256) : (t - 320);
            bx = u & 31; by = u >> 5;
            aRow0 = (size_t)by << 7; bRow0 = (size_t)bx << 7;
            sAe = DD; sBe = DD; Bbase = g_gwt; nkb = DD >> 6;
        }

        // logits tiles: wait for ALL mode-0 tiles to publish g_lA/g_lB
        if (mode == 2) {
            if (tid == 0) {
                while (*(volatile unsigned int*)&g_done_ctr < 256u) __nanosleep(64);
            }
            __syncthreads();
            __threadfence();   // acquire
        }

        auto load_stage = [&](int kb, int slot) {
            int k0 = kb << 6;
            const __nv_bfloat16* Ab = Abase;
            int ka = k0;
            if (mode == 0) { Ab = ((k0 >> 12) == 1) ? g_p_lo : g_p_hi; ka = k0 & 4095; }
            uint32_t sb = sbase + slot * STAGE_BYTES;
#pragma unroll
            for (int rp = 0; rp < 8; ++rp) {
                int r = lrow + (rp << 4);
                int off = (r << 7) + (chunk << 4);
                int sw = off ^ ((off >> 3) & 0x70);
                cp_async16(sb + sw, Ab + (aRow0 + r) * (size_t)sAe + ka + (chunk << 3));
                cp_async16(sb + 16384 + sw, Bbase + (bRow0 + r) * (size_t)sBe + k0 + (chunk << 3));
            }
        };

        float acc[4][8][4];
#pragma unroll
        for (int i = 0; i < 4; ++i)
#pragma unroll
            for (int j = 0; j < 8; ++j)
#pragma unroll
                for (int q = 0; q < 4; ++q) acc[i][j][q] = 0.f;

        // tile prologue: 2 stages in flight
        load_stage(0, 0); cp_commit();
        load_stage(1, 1); cp_commit();
        cp_wait<1>();        // own group 0 done
        __syncthreads();     // slot 0 visible to all threads

        uint32_t afr[2][4][4], bfr[2][4][4];

        // pre-load ks=0 fragments of block 0
        {
            uint32_t sA0 = sbase, sB0 = sbase + 16384;
#pragma unroll
            for (int mt = 0; mt < 4; ++mt) {
                int off = ((m_off + (mt << 4) + arow) << 7) + acolb;
                ldsm_x4(afr[0][mt], sA0 + (off ^ ((off >> 3) & 0x70)));
            }
#pragma unroll
            for (int ntp = 0; ntp < 4; ++ntp) {
                int off = ((n_off + (ntp << 4) + brow) << 7) + bcolb;
                ldsm_x4(bfr[0][ntp], sB0 + (off ^ ((off >> 3) & 0x70)));
            }
        }

        for (int kb = 0; kb < nkb; ++kb) {
            uint32_t sA = sbase + (kb % STAGES) * STAGE_BYTES;
            uint32_t sB = sA + 16384;

            // ks=0 fragments already resident (loaded pre-barrier last iter / prologue)
            if (kb + 2 < nkb) load_stage(kb + 2, (kb + 2) % STAGES);
            cp_commit();

            // ks = 0..2 with fragment prefetch; all smem reads of slot kb done by end of ks=2
#pragma unroll
            for (int ks = 0; ks < 3; ++ks) {
                int nb = (ks + 1) & 1;
#pragma unroll
                for (int mt = 0; mt < 4; ++mt) {
                    int off = ((m_off + (mt << 4) + arow) << 7) + ((ks + 1) << 5) + acolb;
                    ldsm_x4(afr[nb][mt], sA + (off ^ ((off >> 3) & 0x70)));
                }
#pragma unroll
                for (int ntp = 0; ntp < 4; ++ntp) {
                    int off = ((n_off + (ntp << 4) + brow) << 7) + ((ks + 1) << 5) + bcolb;
                    ldsm_x4(bfr[nb][ntp], sB + (off ^ ((off >> 3) & 0x70)));
                }
                int cb = ks & 1;
#pragma unroll
                for (int mt = 0; mt < 4; ++mt)
#pragma unroll
                    for (int nt = 0; nt < 8; ++nt)
                        mma16816(acc[mt][nt], afr[cb][mt], bfr[cb][nt >> 1] + ((nt & 1) << 1));
            }

            cp_wait<1>();      // group kb+1 done (only just-committed group may pend)
            __syncthreads();   // slot kb+1 visible; slot kb readers all done (pre-barrier)

            // cross-block pipeline: load ks=0 fragments of block kb+1 from slot kb+1,
            // then the 32 ks=3 MMAs (buffer [1]) cover the LDSM latency.
            {
                uint32_t sAn = sbase + ((kb + 1) % STAGES) * STAGE_BYTES;
                uint32_t sBn = sAn + 16384;
#pragma unroll
                for (int mt = 0; mt < 4; ++mt) {
                    int off = ((m_off + (mt << 4) + arow) << 7) + acolb;
                    ldsm_x4(afr[0][mt], sAn + (off ^ ((off >> 3) & 0x70)));
                }
#pragma unroll
                for (int ntp = 0; ntp < 4; ++ntp) {
                    int off = ((n_off + (ntp << 4) + brow) << 7) + bcolb;
                    ldsm_x4(bfr[0][ntp], sBn + (off ^ ((off >> 3) & 0x70)));
                }
            }
#pragma unroll
            for (int mt = 0; mt < 4; ++mt)
#pragma unroll
                for (int nt = 0; nt < 8; ++nt)
                    mma16816(acc[mt][nt], afr[1][mt], bfr[1][nt >> 1] + ((nt & 1) << 1));
        }

        // epilogue
        if (mode == 0) {
            // fused bias + hi/lo split straight into logits operands.
            const bool is_theta = (bx < 4);
            const float* __restrict__ bias = is_theta ? theta_b : f_b;
            __nv_bfloat16* __restrict__ dst = is_theta ? g_lA : g_lB;
#pragma unroll
            for (int nt = 0; nt < 8; ++nt) {
                int e = (int)((bRow0 + n_off + (nt << 3) + ((lane & 3) << 1)) & 511);
                float b0 = bias[e], b1 = bias[e + 1];
#pragma unroll
                for (int mt = 0; mt < 4; ++mt) {
                    size_t r0 = aRow0 + m_off + (mt << 4) + (lane >> 2);
#pragma unroll
                    for (int hh = 0; hh < 2; ++hh) {
                        size_t ro = (r0 + (size_t)(hh << 3)) * KLOG;
                        float v0 = acc[mt][nt][hh * 2]     + b0;
                        float v1 = acc[mt][nt][hh * 2 + 1] + b1;
                        __nv_bfloat16 h0 = __float2bfloat16(v0);
                        __nv_bfloat16 h1 = __float2bfloat16(v1);
                        __nv_bfloat16 l0 = __float2bfloat16(v0 - __bfloat162float(h0));
                        __nv_bfloat16 l1 = __float2bfloat16(v1 - __bfloat162float(h1));
                        __nv_bfloat162 hp(h0, h1), lp(l0, l1);
                        *(__nv_bfloat162*)(dst + ro + e) = hp;
                        if (is_theta) {
                            *(__nv_bfloat162*)(dst + ro + 512 + e)  = lp;
                            *(__nv_bfloat162*)(dst + ro + 1024 + e) = hp;
                        } else {
                            *(__nv_bfloat162*)(dst + ro + 512 + e)  = hp;
                            *(__nv_bfloat162*)(dst + ro + 1024 + e) = lp;
                        }
                    }
                }
            }
            // publish completion (release)
            __threadfence();
            __syncthreads();
            if (tid == 0) atomicAdd(&g_done_ctr, 1u);
        } else if (mode == 1) {
#pragma unroll
            for (int mt = 0; mt < 4; ++mt) {
                size_t r0 = aRow0 + m_off + (mt << 4) + (lane >> 2);
#pragma unroll
                for (int nt = 0; nt < 8; ++nt) {
                    size_t cix = bRow0 + n_off + (nt << 3) + ((lane & 3) << 1);
                    *(__nv_bfloat162*)(g_gm_bf + r0 * DD + cix) =
                        __nv_bfloat162(__float2bfloat16(acc[mt][nt][0]), __float2bfloat16(acc[mt][nt][1]));
                    *(__nv_bfloat162*)(g_gm_bf + (r0 + 8) * DD + cix) =
                        __nv_bfloat162(__float2bfloat16(acc[mt][nt][2]), __float2bfloat16(acc[mt][nt][3]));
                }
            }
            // publish completion (release)
            __threadfence();
            __syncthreads();
            if (tid == 0) atomicAdd(&g_g_done[by], 1u);
        } else {
            // logits: raw fp32 to g_att
#pragma unroll
            for (int mt = 0; mt < 4; ++mt) {
                size_t r0 = aRow0 + m_off + (mt << 4) + (lane >> 2);
#pragma unroll
                for (int nt = 0; nt < 8; ++nt) {
                    int cix = q0 + n_off + (nt << 3) + ((lane & 3) << 1);
                    *(float2*)(g_att + r0 * PP + cix) = make_float2(acc[mt][nt][0], acc[mt][nt][1]);
                    *(float2*)(g_att + (r0 + 8) * PP + cix) = make_float2(acc[mt][nt][2], acc[mt][nt][3]);
                }
            }
            // publish completion (release)
            __threadfence();
            __syncthreads();
            if (tid == 0) atomicAdd(&g_l_done[l_band], 1u);
        }
    }
}

// ---------------- launcher ----------------
extern "C" void kernel_launch(void* const* d_in, const int* in_sizes, int n_in,
                              void* d_out, int out_size) {
    (void)in_sizes; (void)n_in; (void)out_size;
    const float* x       = (const float*)d_in[0];
    const float* theta_w = (const float*)d_in[1];
    const float* theta_b = (const float*)d_in[2];
    const float* f_w     = (const float*)d_in[3];
    const float* f_b     = (const float*)d_in[4];
    const float* gw      = (const float*)d_in[5];
    const float* gb      = (const float*)d_in[6];
    const float* scale   = (const float*)d_in[7];
    float* out = (float*)d_out;

    cudaFuncSetAttribute(gemm_hmma_kernel,
                         cudaFuncAttributeMaxDynamicSharedMemorySize, GEMM_SMEM);

    prep_kernel<<<36864, 256>>>(x, theta_w, f_w, gw);            // prep + weight transforms (+counter reset)
    gemm_hmma_kernel<<<304, 128, GEMM_SMEM>>>(theta_b, f_b, x, gb, scale, out);  // everything else
}

// round 17
// speedup vs baseline: 1.2697x; 1.2697x over previous
#include <cuda_runtime.h>
#include <cuda_bf16.h>
#include <cstdint>

// Problem constants
#define BB 16
#define CC 16
#define PP 256          // patches per image (16x16)
#define DD 4096         // flattened patch dim
#define EE 512          // embedding dim
#define MROWS 4096      // B*P
#define N1 1024         // theta|f concat
#define KSTACK 12288    // 3*DD (hi/lo stacked K)
#define KLOG 1536       // 3*EE (hi/lo stacked logits K)
#define NTILES 1344     // 256 mode0 + 1024 mode1 + 64 logits

// ---------------- scratch (device globals; no allocation allowed) ----------------
__device__ __nv_bfloat16 g_p_hi[(size_t)MROWS * DD];
__device__ __nv_bfloat16 g_p_lo[(size_t)MROWS * DD];
__device__ __nv_bfloat16 g_w1t[(size_t)N1 * KSTACK];      // [n, kstack]: Whi | Whi | Wlo
__device__ __nv_bfloat16 g_gwt[(size_t)DD * DD];          // g_w transposed [n, k]
__device__ __nv_bfloat16 g_lA[(size_t)MROWS * KLOG];      // [thetahi | thetalo | thetahi] (+bias)
__device__ __nv_bfloat16 g_lB[(size_t)MROWS * KLOG];      // [fhi | fhi | flo] (+bias)
__device__ __nv_bfloat16 g_gm_bf[(size_t)MROWS * DD];     // g = p @ g_w (bf16)
__device__ float g_att[(size_t)BB * PP * PP];             // raw logits
__device__ unsigned int g_tile_ctr;                       // persistent-GEMM work counter
__device__ unsigned int g_done_ctr;                       // mode-0 tile completions

__device__ __forceinline__ uint32_t smem_u32(const void* p) {
    uint32_t a;
    asm("{ .reg .u64 t; cvta.to.shared.u64 t, %1; cvt.u32.u64 %0, t; }" : "=r"(a) : "l"(p));
    return a;
}
__device__ __forceinline__ void cp_async16(uint32_t saddr, const void* gptr) {
    asm volatile("cp.async.cg.shared.global [%0], [%1], 16;" :: "r"(saddr), "l"(gptr));
}
__device__ __forceinline__ void cp_commit() {
    asm volatile("cp.async.commit_group;");
}
template <int N>
__device__ __forceinline__ void cp_wait() {
    asm volatile("cp.async.wait_group %0;" :: "n"(N));
}
__device__ __forceinline__ void ldsm_x4(uint32_t* r, uint32_t addr) {
    asm volatile("ldmatrix.sync.aligned.m8n8.x4.shared.b16 {%0,%1,%2,%3}, [%4];"
                 : "=r"(r[0]), "=r"(r[1]), "=r"(r[2]), "=r"(r[3]) : "r"(addr));
}
__device__ __forceinline__ void mma16816(float* d, const uint32_t* a, const uint32_t* b) {
    asm volatile(
        "mma.sync.aligned.m16n8k16.row.col.f32.bf16.bf16.f32 "
        "{%0,%1,%2,%3}, {%4,%5,%6,%7}, {%8,%9}, {%0,%1,%2,%3};"
        : "+f"(d[0]), "+f"(d[1]), "+f"(d[2]), "+f"(d[3])
        : "r"(a[0]), "r"(a[1]), "r"(a[2]), "r"(a[3]), "r"(b[0]), "r"(b[1]));
}

// ---------------- kernel 1: prep (patch extract + hi/lo) MERGED with weight transforms ----------------
__global__ __launch_bounds__(256) void prep_kernel(const float* __restrict__ x,
                                                   const float* __restrict__ theta_w,
                                                   const float* __restrict__ f_w,
                                                   const float* __restrict__ gw) {
    const int bid = blockIdx.x;
    const int tid = threadIdx.x;
    if (bid == 0 && tid == 0) { g_tile_ctr = 0u; g_done_ctr = 0u; }   // reset counters each replay
    if (bid < 16384) {
        // patch extract + bf16 hi/lo split
        size_t i4 = (size_t)bid * 256 + tid;
        size_t e0 = i4 << 2;  // element index into p [4096, 4096]
        int d   = (int)(e0 & 4095);
        int row = (int)(e0 >> 12);
        int b = row >> 8, p = row & 255;
        int pi = p >> 4, pj = p & 15;
        int c = d >> 8, rem = d & 255;
        int ih = rem >> 4, iw = rem & 15;
        size_t xi = (((((size_t)b * CC + c) << 8) + (pi << 4) + ih) << 8) + (pj << 4) + iw;
        float4 v = *(const float4*)(x + xi);
        float vv[4] = {v.x, v.y, v.z, v.w};
        __nv_bfloat16 h[4], l[4];
#pragma unroll
        for (int j = 0; j < 4; ++j) {
            h[j] = __float2bfloat16(vv[j]);
            l[j] = __float2bfloat16(vv[j] - __bfloat162float(h[j]));
        }
        ((__nv_bfloat162*)(g_p_hi + e0))[0] = __nv_bfloat162(h[0], h[1]);
        ((__nv_bfloat162*)(g_p_hi + e0))[1] = __nv_bfloat162(h[2], h[3]);
        ((__nv_bfloat162*)(g_p_lo + e0))[0] = __nv_bfloat162(l[0], l[1]);
        ((__nv_bfloat162*)(g_p_lo + e0))[1] = __nv_bfloat162(l[2], l[3]);
    } else {
        // weight transforms (32x32 transpose tiles, 256 threads do 8 rows/pass)
        __shared__ float s[32][33];
        int wb = bid - 16384;            // 0..20479
        int k0 = (wb & 127) << 5;
        int wy = wb >> 7;                // 0..159
        int tx = tid & 31, tg = tid >> 5;
        if (wy < 32) {
            int n0 = wy << 5;
            int n = n0 + tx;
#pragma unroll
            for (int rr = tg; rr < 32; rr += 8)
                s[rr][tx] = (n < EE) ? theta_w[(size_t)(k0 + rr) * EE + n]
                                     : f_w[(size_t)(k0 + rr) * EE + (n - EE)];
            __syncthreads();
#pragma unroll
            for (int rr = tg; rr < 32; rr += 8) {
                int k = k0 + tx, nn = n0 + rr;
                float w = s[tx][rr];
                __nv_bfloat16 hi = __float2bfloat16(w);
                __nv_bfloat16 lo = __float2bfloat16(w - __bfloat162float(hi));
                size_t base = (size_t)nn * KSTACK + k;
                g_w1t[base]        = hi;
                g_w1t[base + 4096] = hi;
                g_w1t[base + 8192] = lo;
            }
        } else {
            int n0 = (wy - 32) << 5;
#pragma unroll
            for (int rr = tg; rr < 32; rr += 8)
                s[rr][tx] = gw[(size_t)(k0 + rr) * DD + (n0 + tx)];
            __syncthreads();
#pragma unroll
            for (int rr = tg; rr < 32; rr += 8)
                g_gwt[(size_t)(n0 + rr) * DD + (k0 + tx)] = __float2bfloat16(s[tx][rr]);
        }
    }
}

// ---------------- kernel 2: persistent merged HMMA GEMM (3 tile modes) ----------------
// t <  256          : mode0 TF = [p_hi|p_lo|p_hi] @ W1t^T (K=12288) -> bias + hi/lo split into g_lA/g_lB
// 256<=t<448, 512<= : mode1 g  = p_hi @ gwt^T             (K=4096)  -> bf16 g_gm_bf
// 448<=t<512        : mode2 logits = lA @ lB^T            (K=1536)  -> fp32 g_att (waits for all mode0)
#define STAGES 3
#define STAGE_BYTES 32768      // A tile 16KB + B tile 16KB
#define GEMM_SMEM (STAGES * STAGE_BYTES + 16)

__global__ __launch_bounds__(128, 2) void gemm_hmma_kernel(const float* __restrict__ theta_b,
                                                           const float* __restrict__ f_b) {
    extern __shared__ __align__(1024) char smem[];
    int* s_tile = (int*)(smem + STAGES * STAGE_BYTES);

    const int tid = threadIdx.x;
    const int lane = tid & 31, wid = tid >> 5;
    const uint32_t sbase = smem_u32(smem);

    const int chunk = tid & 7;       // 8 chunks of 16B per 128B row
    const int lrow  = tid >> 3;      // 0..15

    // warp tiling: 2 (M) x 2 (N) warps; warp tile 64x64
    const int m_off = (wid & 1) << 6;
    const int n_off = (wid >> 1) << 6;
    const int arow  = lane & 15;
    const int acolb = (lane >> 4) << 4;
    const int brow  = (lane & 7) + ((lane >> 4) << 3);
    const int bcolb = (lane & 8) << 1;

    while (true) {
        if (tid == 0) *s_tile = (int)atomicAdd(&g_tile_ctr, 1u);
        __syncthreads();          // broadcast tile id; also fences previous tile's smem reads
        const int t = *s_tile;
        if (t >= NTILES) break;

        int mode, bx = 0, by = 0, q0 = 0;
        size_t aRow0, bRow0;
        int sAe, sBe, nkb;
        const __nv_bfloat16 *Abase = g_p_hi, *Bbase;

        if (t < 256) {
            mode = 0; bx = t & 7; by = t >> 3;
            aRow0 = (size_t)by << 7; bRow0 = (size_t)bx << 7;
            sAe = DD; sBe = KSTACK; Bbase = g_w1t; nkb = KSTACK >> 6;
        } else if (t >= 448 && t < 512) {
            mode = 2;
            int u = t - 448;
            int b = u >> 2;
            aRow0 = (size_t)b * PP + (size_t)((u >> 1) & 1) * 128;
            q0 = (u & 1) << 7;
            bRow0 = (size_t)b * PP + q0;
            sAe = KLOG; sBe = KLOG; Abase = g_lA; Bbase = g_lB; nkb = KLOG >> 6;
        } else {
            mode = 1;
            int u = (t < 448) ? (t - 256) : (t - 320);
            bx = u & 31; by = u >> 5;
            aRow0 = (size_t)by << 7; bRow0 = (size_t)bx << 7;
            sAe = DD; sBe = DD; Bbase = g_gwt; nkb = DD >> 6;
        }

        // logits tiles: wait for ALL mode-0 tiles to publish g_lA/g_lB
        if (mode == 2) {
            if (tid == 0) {
                while (*(volatile unsigned int*)&g_done_ctr < 256u) __nanosleep(64);
            }
            __syncthreads();
            __threadfence();   // acquire
        }

        auto load_stage = [&](int kb, int slot) {
            int k0 = kb << 6;
            const __nv_bfloat16* Ab = Abase;
            int ka = k0;
            if (mode == 0) { Ab = ((k0 >> 12) == 1) ? g_p_lo : g_p_hi; ka = k0 & 4095; }
            uint32_t sb = sbase + slot * STAGE_BYTES;
#pragma unroll
            for (int rp = 0; rp < 8; ++rp) {
                int r = lrow + (rp << 4);
                int off = (r << 7) + (chunk << 4);
                int sw = off ^ ((off >> 3) & 0x70);
                cp_async16(sb + sw, Ab + (aRow0 + r) * (size_t)sAe + ka + (chunk << 3));
                cp_async16(sb + 16384 + sw, Bbase + (bRow0 + r) * (size_t)sBe + k0 + (chunk << 3));
            }
        };

        float acc[4][8][4];
#pragma unroll
        for (int i = 0; i < 4; ++i)
#pragma unroll
            for (int j = 0; j < 8; ++j)
#pragma unroll
                for (int q = 0; q < 4; ++q) acc[i][j][q] = 0.f;

        // tile prologue: 2 stages in flight
        load_stage(0, 0); cp_commit();
        load_stage(1, 1); cp_commit();
        cp_wait<1>();        // own group 0 done
        __syncthreads();     // slot 0 visible to all threads

        uint32_t afr[2][4][4], bfr[2][4][4];

        // pre-load ks=0 fragments of block 0
        {
            uint32_t sA0 = sbase, sB0 = sbase + 16384;
#pragma unroll
            for (int mt = 0; mt < 4; ++mt) {
                int off = ((m_off + (mt << 4) + arow) << 7) + acolb;
                ldsm_x4(afr[0][mt], sA0 + (off ^ ((off >> 3) & 0x70)));
            }
#pragma unroll
            for (int ntp = 0; ntp < 4; ++ntp) {
                int off = ((n_off + (ntp << 4) + brow) << 7) + bcolb;
                ldsm_x4(bfr[0][ntp], sB0 + (off ^ ((off >> 3) & 0x70)));
            }
        }

        for (int kb = 0; kb < nkb; ++kb) {
            uint32_t sA = sbase + (kb % STAGES) * STAGE_BYTES;
            uint32_t sB = sA + 16384;

            // ks=0 fragments already resident (loaded pre-barrier last iter / prologue)
            if (kb + 2 < nkb) load_stage(kb + 2, (kb + 2) % STAGES);
            cp_commit();

            // ks = 0..2 with fragment prefetch; all smem reads of slot kb done by end of ks=2
#pragma unroll
            for (int ks = 0; ks < 3; ++ks) {
                int nb = (ks + 1) & 1;
#pragma unroll
                for (int mt = 0; mt < 4; ++mt) {
                    int off = ((m_off + (mt << 4) + arow) << 7) + ((ks + 1) << 5) + acolb;
                    ldsm_x4(afr[nb][mt], sA + (off ^ ((off >> 3) & 0x70)));
                }
#pragma unroll
                for (int ntp = 0; ntp < 4; ++ntp) {
                    int off = ((n_off + (ntp << 4) + brow) << 7) + ((ks + 1) << 5) + bcolb;
                    ldsm_x4(bfr[nb][ntp], sB + (off ^ ((off >> 3) & 0x70)));
                }
                int cb = ks & 1;
#pragma unroll
                for (int mt = 0; mt < 4; ++mt)
#pragma unroll
                    for (int nt = 0; nt < 8; ++nt)
                        mma16816(acc[mt][nt], afr[cb][mt], bfr[cb][nt >> 1] + ((nt & 1) << 1));
            }

            cp_wait<1>();      // group kb+1 done (only just-committed group may pend)
            __syncthreads();   // slot kb+1 visible; slot kb readers all done (pre-barrier)

            // cross-block pipeline: load ks=0 fragments of block kb+1 from slot kb+1,
            // then the 32 ks=3 MMAs (buffer [1]) cover the LDSM latency.
            {
                uint32_t sAn = sbase + ((kb + 1) % STAGES) * STAGE_BYTES;
                uint32_t sBn = sAn + 16384;
#pragma unroll
                for (int mt = 0; mt < 4; ++mt) {
                    int off = ((m_off + (mt << 4) + arow) << 7) + acolb;
                    ldsm_x4(afr[0][mt], sAn + (off ^ ((off >> 3) & 0x70)));
                }
#pragma unroll
                for (int ntp = 0; ntp < 4; ++ntp) {
                    int off = ((n_off + (ntp << 4) + brow) << 7) + bcolb;
                    ldsm_x4(bfr[0][ntp], sBn + (off ^ ((off >> 3) & 0x70)));
                }
            }
#pragma unroll
            for (int mt = 0; mt < 4; ++mt)
#pragma unroll
                for (int nt = 0; nt < 8; ++nt)
                    mma16816(acc[mt][nt], afr[1][mt], bfr[1][nt >> 1] + ((nt & 1) << 1));
        }

        // epilogue
        if (mode == 0) {
            // fused bias + hi/lo split straight into logits operands.
            const bool is_theta = (bx < 4);
            const float* __restrict__ bias = is_theta ? theta_b : f_b;
            __nv_bfloat16* __restrict__ dst = is_theta ? g_lA : g_lB;
#pragma unroll
            for (int nt = 0; nt < 8; ++nt) {
                int e = (int)((bRow0 + n_off + (nt << 3) + ((lane & 3) << 1)) & 511);
                float b0 = bias[e], b1 = bias[e + 1];
#pragma unroll
                for (int mt = 0; mt < 4; ++mt) {
                    size_t r0 = aRow0 + m_off + (mt << 4) + (lane >> 2);
#pragma unroll
                    for (int hh = 0; hh < 2; ++hh) {
                        size_t ro = (r0 + (size_t)(hh << 3)) * KLOG;
                        float v0 = acc[mt][nt][hh * 2]     + b0;
                        float v1 = acc[mt][nt][hh * 2 + 1] + b1;
                        __nv_bfloat16 h0 = __float2bfloat16(v0);
                        __nv_bfloat16 h1 = __float2bfloat16(v1);
                        __nv_bfloat16 l0 = __float2bfloat16(v0 - __bfloat162float(h0));
                        __nv_bfloat16 l1 = __float2bfloat16(v1 - __bfloat162float(h1));
                        __nv_bfloat162 hp(h0, h1), lp(l0, l1);
                        *(__nv_bfloat162*)(dst + ro + e) = hp;
                        if (is_theta) {
                            *(__nv_bfloat162*)(dst + ro + 512 + e)  = lp;
                            *(__nv_bfloat162*)(dst + ro + 1024 + e) = hp;
                        } else {
                            *(__nv_bfloat162*)(dst + ro + 512 + e)  = hp;
                            *(__nv_bfloat162*)(dst + ro + 1024 + e) = lp;
                        }
                    }
                }
            }
            // publish completion (release)
            __threadfence();
            __syncthreads();
            if (tid == 0) atomicAdd(&g_done_ctr, 1u);
        } else if (mode == 1) {
#pragma unroll
            for (int mt = 0; mt < 4; ++mt) {
                size_t r0 = aRow0 + m_off + (mt << 4) + (lane >> 2);
#pragma unroll
                for (int nt = 0; nt < 8; ++nt) {
                    size_t cix = bRow0 + n_off + (nt << 3) + ((lane & 3) << 1);
                    *(__nv_bfloat162*)(g_gm_bf + r0 * DD + cix) =
                        __nv_bfloat162(__float2bfloat16(acc[mt][nt][0]), __float2bfloat16(acc[mt][nt][1]));
                    *(__nv_bfloat162*)(g_gm_bf + (r0 + 8) * DD + cix) =
                        __nv_bfloat162(__float2bfloat16(acc[mt][nt][2]), __float2bfloat16(acc[mt][nt][3]));
                }
            }
        } else {
            // logits: raw fp32 to g_att
#pragma unroll
            for (int mt = 0; mt < 4; ++mt) {
                size_t r0 = aRow0 + m_off + (mt << 4) + (lane >> 2);
#pragma unroll
                for (int nt = 0; nt < 8; ++nt) {
                    int cix = q0 + n_off + (nt << 3) + ((lane & 3) << 1);
                    *(float2*)(g_att + r0 * PP + cix) = make_float2(acc[mt][nt][0], acc[mt][nt][1]);
                    *(float2*)(g_att + (r0 + 8) * PP + cix) = make_float2(acc[mt][nt][2], acc[mt][nt][3]);
                }
            }
        }
    }
}

// ---------------- kernel 3: fused softmax + gating epilogue ----------------
// block = one (b,p) row: softmax over 256 raw logits, then out = scale*w*(g+gb)+x for 16 c-planes.
__global__ __launch_bounds__(256) void epilogue_kernel(const float* __restrict__ x,
                                                       const float* __restrict__ gb,
                                                       const float* __restrict__ scale,
                                                       float* __restrict__ out) {
    int row = blockIdx.x;         // b*256 + p
    int t = threadIdx.x;
    __shared__ float sw[256];
    __shared__ float smax[8], ssum[8];

    float v = g_att[(size_t)row * PP + t];
    float m = v;
#pragma unroll
    for (int o = 16; o; o >>= 1) m = fmaxf(m, __shfl_xor_sync(0xffffffffu, m, o));
    if ((t & 31) == 0) smax[t >> 5] = m;
    __syncthreads();
    float M = smax[0];
#pragma unroll
    for (int i = 1; i < 8; ++i) M = fmaxf(M, smax[i]);
    float e = __expf(v - M);
    float s = e;
#pragma unroll
    for (int o = 16; o; o >>= 1) s += __shfl_xor_sync(0xffffffffu, s, o);
    if ((t & 31) == 0) ssum[t >> 5] = s;
    __syncthreads();
    float S = 0.f;
#pragma unroll
    for (int i = 0; i < 8; ++i) S += ssum[i];
    sw[t] = e / S;
    __syncthreads();

    int b = row >> 8, p = row & 255;
    int pi = p >> 4, pj = p & 15;
    int n0 = (t & 63) << 2;           // n quad
    int ih = n0 >> 4, iw = n0 & 15;
    int cb = t >> 6;                  // 0..3
    float4 wv = *(const float4*)(sw + n0);
    float sc = scale[0];
#pragma unroll
    for (int i = 0; i < 4; ++i) {
        int c = (i << 2) + cb;
        const __nv_bfloat162* gp = (const __nv_bfloat162*)(g_gm_bf + (size_t)row * DD + (c << 8) + n0);
        __nv_bfloat162 g01 = gp[0], g23 = gp[1];
        float4 gbv = *(const float4*)(gb + (c << 8) + n0);
        size_t xo = (((size_t)(b * CC + c) * 256 + (pi * 16 + ih)) * 256) + pj * 16 + iw;
        float4 xv = *(const float4*)(x + xo);
        float4 o4;
        o4.x = sc * wv.x * (__bfloat162float(g01.x) + gbv.x) + xv.x;
        o4.y = sc * wv.y * (__bfloat162float(g01.y) + gbv.y) + xv.y;
        o4.z = sc * wv.z * (__bfloat162float(g23.x) + gbv.z) + xv.z;
        o4.w = sc * wv.w * (__bfloat162float(g23.y) + gbv.w) + xv.w;
        *(float4*)(out + xo) = o4;
    }
}

// ---------------- launcher ----------------
extern "C" void kernel_launch(void* const* d_in, const int* in_sizes, int n_in,
                              void* d_out, int out_size) {
    (void)in_sizes; (void)n_in; (void)out_size;
    const float* x       = (const float*)d_in[0];
    const float* theta_w = (const float*)d_in[1];
    const float* theta_b = (const float*)d_in[2];
    const float* f_w     = (const float*)d_in[3];
    const float* f_b     = (const float*)d_in[4];
    const float* gw      = (const float*)d_in[5];
    const float* gb      = (const float*)d_in[6];
    const float* scale   = (const float*)d_in[7];
    float* out = (float*)d_out;

    cudaFuncSetAttribute(gemm_hmma_kernel,
                         cudaFuncAttributeMaxDynamicSharedMemorySize, GEMM_SMEM);

    prep_kernel<<<36864, 256>>>(x, theta_w, f_w, gw);            // prep + weight transforms
    gemm_hmma_kernel<<<304, 128, GEMM_SMEM>>>(theta_b, f_b);     // TF + g + logits, persistent
    epilogue_kernel<<<4096, 256>>>(x, gb, scale, out);           // softmax + gate + residual
}